// round 14
// baseline (speedup 1.0000x reference)
#include <cuda_runtime.h>
#include <stdint.h>

// Problem constants (fixed by the reference).
#define MM      512      // checks
#define NN      1024     // variables
#define EE      3072     // edges
#define NITERS  10
#define THREADS 512
#define WB      4                 // batch lanes per thread (float4; 2 packed f32x2 pairs)
#define CSTRIDE 7                 // float4 slots per check (112B stride -> conflict-free)
#define CSLOTS  (MM * CSTRIDE)    // 3584 float4 per buffer; slot 6 of each check = llr pad

#define LOG2E 1.4426950408889634f
#define LN2   0.6931471805599453f
#define CLIP  0.999995f
#define UCLAMP 24.0f              // upper clamp on log2-domain sum (overflow guard)

typedef unsigned long long u64;

// ---------------- device-global scratch (no runtime allocation) --------------
// Iteration-varying weights, TRANSPOSED to per-check coalesced layout:
__device__ __align__(16) float4 g_wA[NITERS * MM];   // {w[e0][0],w[e0][1],w[e1][0],w[e1][1]}
__device__ __align__(16) float4 g_wB[NITERS * MM];   // edges 2,3
__device__ __align__(16) float4 g_wC[NITERS * MM];   // edges 4,5
__device__ __align__(16) float4 g_lwA[NITERS * MM];  // lw(var(e0..e3)) * log2e
__device__ __align__(8)  float2 g_lwB[NITERS * MM];  // lw(var(e4..e5)) * log2e
// Iteration-invariant topology (loaded once into registers):
__device__ __align__(16) uint4 g_idxA[MM];           // packed extrinsic slot pairs, edges 0..3
__device__ __align__(8)  uint2 g_idxB[MM];           // edges 4,5
__device__ __align__(16) uint4 g_vsl[MM];            // packed u16 llr PAD slots (6 used)
__device__ uint2  g_finidx[MM];
__device__ float4 g_finw[MM];                        // {wf0*ln2, wf1*ln2, wf2*ln2, llr_final}

__device__ __forceinline__ int slot7(int e) { return (e / 6) * CSTRIDE + (e % 6); }
// llr pad slot for variable v: buffer (v&1), check (v>>1), slot 6. Absolute index.
__device__ __forceinline__ int pslot(int v) {
    return (v & 1) * CSLOTS + (v >> 1) * CSTRIDE + 6;
}

// ---------------------------------- prep -------------------------------------
__global__ void prep_kernel(const float* __restrict__ w_iter,
                            const float* __restrict__ llr_iter,
                            const float* __restrict__ w_final,
                            const float* __restrict__ llr_final,
                            const int*   __restrict__ v_sum,
                            const int*   __restrict__ edge_var,
                            const int*   __restrict__ fin_idx) {
    int t = blockIdx.x * blockDim.x + threadIdx.x;
    if (t < NITERS * MM) {
        int it = t / MM, r = t % MM;
        const float* wi = w_iter + it * (EE * 2) + 12 * r;   // 2 weights per edge, 6 edges
        g_wA[t] = make_float4(wi[0], wi[1], wi[2],  wi[3]);
        g_wB[t] = make_float4(wi[4], wi[5], wi[6],  wi[7]);
        g_wC[t] = make_float4(wi[8], wi[9], wi[10], wi[11]);
        const float* li = llr_iter + it * NN;
        const int* ev = edge_var + 6 * r;
        g_lwA[t] = make_float4(li[ev[0]] * LOG2E, li[ev[1]] * LOG2E,
                               li[ev[2]] * LOG2E, li[ev[3]] * LOG2E);
        g_lwB[t] = make_float2(li[ev[4]] * LOG2E, li[ev[5]] * LOG2E);
    }
    if (t < MM) {
        int e0 = 6 * t;
        unsigned pk6[6];
#pragma unroll
        for (int j = 0; j < 6; j++)
            pk6[j] = (unsigned)slot7(v_sum[2 * (e0 + j)]) |
                     ((unsigned)slot7(v_sum[2 * (e0 + j) + 1]) << 16);
        g_idxA[t] = make_uint4(pk6[0], pk6[1], pk6[2], pk6[3]);
        g_idxB[t] = make_uint2(pk6[4], pk6[5]);
        const int* ev = edge_var + e0;
        g_vsl[t] = make_uint4(
            (unsigned)pslot(ev[0]) | ((unsigned)pslot(ev[1]) << 16),
            (unsigned)pslot(ev[2]) | ((unsigned)pslot(ev[3]) << 16),
            (unsigned)pslot(ev[4]) | ((unsigned)pslot(ev[5]) << 16), 0u);
        g_finidx[t] = make_uint2((unsigned)slot7(fin_idx[3 * t]) |
                                 ((unsigned)slot7(fin_idx[3 * t + 1]) << 16),
                                 (unsigned)slot7(fin_idx[3 * t + 2]));
        g_finw[t] = make_float4(w_final[3 * t] * LN2, w_final[3 * t + 1] * LN2,
                                w_final[3 * t + 2] * LN2, llr_final[t]);
    }
}

// ------------------------------- fast math -----------------------------------
__device__ __forceinline__ float ex2f_(float x) { float y; asm("ex2.approx.f32 %0, %1;" : "=f"(y) : "f"(x)); return y; }
__device__ __forceinline__ float lg2f_(float x) { float y; asm("lg2.approx.f32 %0, %1;" : "=f"(y) : "f"(x)); return y; }
__device__ __forceinline__ float rcpf_(float x) { float y; asm("rcp.approx.f32 %0, %1;" : "=f"(y) : "f"(x)); return y; }

// ---- packed f32x2 (Blackwell) ----
__device__ __forceinline__ u64 pk2(float lo, float hi) {
    u64 r;
    asm("mov.b64 %0, {%1, %2};" : "=l"(r)
        : "r"(__float_as_uint(lo)), "r"(__float_as_uint(hi)));
    return r;
}
__device__ __forceinline__ void upk2(u64 v, float& lo, float& hi) {
    unsigned x, y;
    asm("mov.b64 {%0, %1}, %2;" : "=r"(x), "=r"(y) : "l"(v));
    lo = __uint_as_float(x); hi = __uint_as_float(y);
}
__device__ __forceinline__ u64 fma2_(u64 a, u64 b, u64 c) {
    u64 d; asm("fma.rn.f32x2 %0, %1, %2, %3;" : "=l"(d) : "l"(a), "l"(b), "l"(c)); return d;
}
__device__ __forceinline__ u64 mul2_(u64 a, u64 b) {
    u64 d; asm("mul.rn.f32x2 %0, %1, %2;" : "=l"(d) : "l"(a), "l"(b)); return d;
}
__device__ __forceinline__ u64 add2_(u64 a, u64 b) {
    u64 d; asm("add.rn.f32x2 %0, %1, %2;" : "=l"(d) : "l"(a), "l"(b)); return d;
}

#define ONE2P   0x3F8000003F800000ULL   // {1.0f, 1.0f}
#define NONE2P  0xBF800000BF800000ULL   // {-1.0f, -1.0f}

// msg (2 lanes) = lg2(B + c*A) - lg2(B - c*A), packed until the LG2s.
__device__ __forceinline__ float2 lgmsg(u64 B, u64 A, u64 C2, u64 NC2) {
    u64 U = fma2_(C2, A, B);
    u64 V = fma2_(NC2, A, B);
    float ua, ub, va, vb;
    upk2(U, ua, ub); upk2(V, va, vb);
    return make_float2(lg2f_(ua) - lg2f_(va), lg2f_(ub) - lg2f_(vb));
}

// check node for one packed lane-pair: half-split extrinsic products of (E+1),(E-1).
// Emits the 6 extrinsic messages into O[0..5].
__device__ __forceinline__ void tree_msgs(const u64* __restrict__ E,
                                          float2* __restrict__ O) {
    const u64 C2 = pk2(CLIP, CLIP), NC2 = pk2(-CLIP, -CLIP);
    u64 ep3 = add2_(E[3], ONE2P), em3 = add2_(E[3], NONE2P);
    u64 ep4 = add2_(E[4], ONE2P), em4 = add2_(E[4], NONE2P);
    u64 ep5 = add2_(E[5], ONE2P), em5 = add2_(E[5], NONE2P);
    u64 p34 = mul2_(ep3, ep4), m34 = mul2_(em3, em4);
    u64 H2p = mul2_(p34, ep5), H2m = mul2_(m34, em5);

    u64 ep0 = add2_(E[0], ONE2P), em0 = add2_(E[0], NONE2P);
    u64 ep1 = add2_(E[1], ONE2P), em1 = add2_(E[1], NONE2P);
    u64 ep2 = add2_(E[2], ONE2P), em2 = add2_(E[2], NONE2P);
    u64 p01 = mul2_(ep0, ep1), m01 = mul2_(em0, em1);
    u64 H1p = mul2_(p01, ep2), H1m = mul2_(m01, em2);

    O[0] = lgmsg(mul2_(mul2_(ep1, ep2), H2p), mul2_(mul2_(em1, em2), H2m), C2, NC2);
    O[1] = lgmsg(mul2_(mul2_(ep0, ep2), H2p), mul2_(mul2_(em0, em2), H2m), C2, NC2);
    O[2] = lgmsg(mul2_(p01, H2p), mul2_(m01, H2m), C2, NC2);
    O[3] = lgmsg(mul2_(mul2_(ep4, ep5), H1p), mul2_(mul2_(em4, em5), H1m), C2, NC2);
    O[4] = lgmsg(mul2_(mul2_(ep3, ep5), H1p), mul2_(mul2_(em3, em5), H1m), C2, NC2);
    O[5] = lgmsg(mul2_(p34, H1p), mul2_(m34, H1m), C2, NC2);
}

// --------------------------------- main --------------------------------------
extern __shared__ float4 s_dyn[];

// One BP iteration: read messages from buffer at rd_off, write to wr_off.
__device__ __forceinline__ void bp_step(float4* __restrict__ s_base, int tid,
                                        int rd_off, int wr_off, int base,
                                        const unsigned* __restrict__ idx,
                                        const int* __restrict__ vsl) {
    const ulonglong2* sb2 = (const ulonglong2*)s_base;

    float4 wA = g_wA[base], wB = g_wB[base], wC = g_wC[base];
    float4 lA = g_lwA[base];
    float2 lB = g_lwB[base];
    float w0[6] = { wA.x, wA.z, wB.x, wB.z, wC.x, wC.z };
    float w1[6] = { wA.y, wA.w, wB.y, wB.w, wC.y, wC.w };
    float lw[6] = { lA.x, lA.y, lA.z, lA.w, lB.x, lB.y };

    u64 EL[6], EH[6];   // packed e^x for lanes {x,y} and {z,w}
#pragma unroll
    for (int j = 0; j < 6; j++) {
        ulonglong2 A  = sb2[rd_off + (idx[j] & 0xFFFFu)];
        ulonglong2 Bv = sb2[rd_off + (idx[j] >> 16)];
        ulonglong2 L  = sb2[vsl[j]];                 // llr pads (absolute)
        u64 w0p = pk2(w0[j], w0[j]);
        u64 w1p = pk2(w1[j], w1[j]);
        u64 lwp = pk2(lw[j], lw[j]);
        u64 uL = fma2_(A.x, w0p, fma2_(Bv.x, w1p, mul2_(L.x, lwp)));
        u64 uH = fma2_(A.y, w0p, fma2_(Bv.y, w1p, mul2_(L.y, lwp)));
        float u0, u1, u2, u3;
        upk2(uL, u0, u1); upk2(uH, u2, u3);
        EL[j] = pk2(ex2f_(fminf(UCLAMP, u0)), ex2f_(fminf(UCLAMP, u1)));
        EH[j] = pk2(ex2f_(fminf(UCLAMP, u2)), ex2f_(fminf(UCLAMP, u3)));
    }

    float2 O0[6], O1[6];
    tree_msgs(EL, O0);
    tree_msgs(EH, O1);

    float4* dst4 = s_base + wr_off + tid * CSTRIDE;
#pragma unroll
    for (int j = 0; j < 6; j++)
        dst4[j] = make_float4(O0[j].x, O0[j].y, O1[j].x, O1[j].y);

    __syncthreads();   // writes visible before next iteration's gathers
}

__global__ void __launch_bounds__(THREADS, 2)
bp_kernel(const float* __restrict__ llr, float* __restrict__ out) {
    float4* s_base = s_dyn;                  // 2 buffers of CSLOTS float4 (112 KB total)
    const int tid = threadIdx.x;
    const long b0 = (long)blockIdx.x * WB;
    const float* llr0 = llr + b0 * NN;

    // zero buf0 (iteration 0 reads zeros from buf0 slots 0..5)
#pragma unroll
    for (int k = 0; k < CSLOTS / THREADS; k++)
        s_base[tid + k * THREADS] = make_float4(0.f, 0.f, 0.f, 0.f);
    __syncthreads();

    // write llr (4 batch lanes per variable) into the pad slots of BOTH buffers
#pragma unroll
    for (int k = 0; k < NN / THREADS; k++) {
        int v = tid + k * THREADS;
        float4 L;
        L.x = llr0[v];
        L.y = llr0[NN + v];
        L.z = llr0[2 * NN + v];
        L.w = llr0[3 * NN + v];
        s_base[pslot(v)] = L;
    }

    // iteration-invariant topology into registers
    uint4 iA = g_idxA[tid];
    uint2 iB = g_idxB[tid];
    uint4 vp = g_vsl[tid];
    unsigned idx[6] = { iA.x, iA.y, iA.z, iA.w, iB.x, iB.y };
    int vsl[6] = { (int)(vp.x & 0xFFFFu), (int)(vp.x >> 16),
                   (int)(vp.y & 0xFFFFu), (int)(vp.y >> 16),
                   (int)(vp.z & 0xFFFFu), (int)(vp.z >> 16) };
    __syncthreads();

    // 10 iterations, ping-pong with compile-time buffer offsets
#pragma unroll 1
    for (int it2 = 0; it2 < NITERS / 2; it2++) {
        bp_step(s_base, tid, 0, CSLOTS, (2 * it2) * MM + tid, idx, vsl);
        bp_step(s_base, tid, CSLOTS, 0, (2 * it2 + 1) * MM + tid, idx, vsl);
    }

    // final marginalization for variable v = tid (outputs are vars 0..511).
    // After it=9 (odd), last writes went to buf0 -> absolute base indices.
    uint2 fi = g_finidx[tid];
    float4 fw = g_finw[tid];
    float4 A  = s_base[fi.x & 0xFFFFu];
    float4 Bv = s_base[fi.x >> 16];
    float4 C  = s_base[fi.y];
    float4 L  = s_base[pslot(tid)];
    float4 o;
    o.x = fmaf(A.x, fw.x, fmaf(Bv.x, fw.y, fmaf(C.x, fw.z, L.x * fw.w)));
    o.y = fmaf(A.y, fw.x, fmaf(Bv.y, fw.y, fmaf(C.y, fw.z, L.y * fw.w)));
    o.z = fmaf(A.z, fw.x, fmaf(Bv.z, fw.y, fmaf(C.z, fw.z, L.z * fw.w)));
    o.w = fmaf(A.w, fw.x, fmaf(Bv.w, fw.y, fmaf(C.w, fw.z, L.w * fw.w)));
    out[(b0 + 0) * MM + tid] = rcpf_(1.0f + ex2f_(-o.x * LOG2E));
    out[(b0 + 1) * MM + tid] = rcpf_(1.0f + ex2f_(-o.y * LOG2E));
    out[(b0 + 2) * MM + tid] = rcpf_(1.0f + ex2f_(-o.z * LOG2E));
    out[(b0 + 3) * MM + tid] = rcpf_(1.0f + ex2f_(-o.w * LOG2E));
}

// ------------------------------ launch ---------------------------------------
extern "C" void kernel_launch(void* const* d_in, const int* in_sizes, int n_in,
                              void* d_out, int out_size) {
    const float* llr       = (const float*)d_in[0];
    const float* w_iter    = (const float*)d_in[1];
    const float* llr_iter  = (const float*)d_in[2];
    const float* w_final   = (const float*)d_in[3];
    const float* llr_final = (const float*)d_in[4];
    const int*   v_sum     = (const int*)d_in[5];
    // d_in[6] = c_prod_idx: redundant (check r owns edges 6r..6r+5 contiguously)
    const int*   edge_var  = (const int*)d_in[7];
    const int*   fin_idx   = (const int*)d_in[8];

    int B = in_sizes[0] / NN;                 // 8192
    size_t smem = (size_t)(2 * CSLOTS) * sizeof(float4);   // 112 KB

    cudaFuncSetAttribute(bp_kernel, cudaFuncAttributeMaxDynamicSharedMemorySize, (int)smem);

    prep_kernel<<<(NITERS * MM + 255) / 256, 256>>>(w_iter, llr_iter, w_final, llr_final,
                                                    v_sum, edge_var, fin_idx);
    bp_kernel<<<B / WB, THREADS, smem>>>(llr, (float*)d_out);
}

// round 17
// speedup vs baseline: 1.6536x; 1.6536x over previous
#include <cuda_runtime.h>
#include <stdint.h>

// Problem constants (fixed by the reference).
#define MM      512      // checks
#define NN      1024     // variables
#define EE      3072     // edges
#define NITERS  10
#define THREADS 512
#define WB      4                 // batch lanes per thread (float4; 2 packed f32x2 pairs)
#define CSTRIDE 7                 // float4 slots per check (112B stride -> conflict-free)
#define CSLOTS  (MM * CSTRIDE)    // 3584 float4 per buffer; slot 6 of each check = llr pad

#define LOG2E 1.4426950408889634f
#define LN2   0.6931471805599453f
#define CLIP  0.999995f
#define UCLAMP 24.0f              // upper clamp on log2-domain sum (overflow guard)

typedef unsigned long long u64;

// ---------------- device-global scratch (no runtime allocation) --------------
// Iteration-varying weights, TRANSPOSED to per-check coalesced layout:
__device__ __align__(16) float4 g_wA[NITERS * MM];   // {w[e0][0],w[e0][1],w[e1][0],w[e1][1]}
__device__ __align__(16) float4 g_wB[NITERS * MM];   // edges 2,3
__device__ __align__(16) float4 g_wC[NITERS * MM];   // edges 4,5
__device__ __align__(16) float4 g_lwA[NITERS * MM];  // lw(var(e0..e3)) * log2e
__device__ __align__(8)  float2 g_lwB[NITERS * MM];  // lw(var(e4..e5)) * log2e
// Iteration-invariant topology (loaded once into registers):
__device__ __align__(16) uint4 g_idxA[MM];           // packed extrinsic slot pairs, edges 0..3
__device__ __align__(8)  uint2 g_idxB[MM];           // edges 4,5
__device__ __align__(16) uint4 g_vsl[MM];            // packed u16 llr PAD slots (6 used)
__device__ uint2  g_finidx[MM];
__device__ float4 g_finw[MM];                        // {wf0*ln2, wf1*ln2, wf2*ln2, llr_final}

__device__ __forceinline__ int slot7(int e) { return (e / 6) * CSTRIDE + (e % 6); }
// llr pad slot for variable v: buffer (v&1), check (v>>1), slot 6. Absolute index.
__device__ __forceinline__ int pslot(int v) {
    return (v & 1) * CSLOTS + (v >> 1) * CSTRIDE + 6;
}

// ---------------------------------- prep -------------------------------------
__global__ void prep_kernel(const float* __restrict__ w_iter,
                            const float* __restrict__ llr_iter,
                            const float* __restrict__ w_final,
                            const float* __restrict__ llr_final,
                            const int*   __restrict__ v_sum,
                            const int*   __restrict__ edge_var,
                            const int*   __restrict__ fin_idx) {
    int t = blockIdx.x * blockDim.x + threadIdx.x;
    if (t < NITERS * MM) {
        int it = t / MM, r = t % MM;
        const float* wi = w_iter + it * (EE * 2) + 12 * r;   // 2 weights per edge, 6 edges
        g_wA[t] = make_float4(wi[0], wi[1], wi[2],  wi[3]);
        g_wB[t] = make_float4(wi[4], wi[5], wi[6],  wi[7]);
        g_wC[t] = make_float4(wi[8], wi[9], wi[10], wi[11]);
        const float* li = llr_iter + it * NN;
        const int* ev = edge_var + 6 * r;
        g_lwA[t] = make_float4(li[ev[0]] * LOG2E, li[ev[1]] * LOG2E,
                               li[ev[2]] * LOG2E, li[ev[3]] * LOG2E);
        g_lwB[t] = make_float2(li[ev[4]] * LOG2E, li[ev[5]] * LOG2E);
    }
    if (t < MM) {
        int e0 = 6 * t;
        unsigned pk6[6];
#pragma unroll
        for (int j = 0; j < 6; j++)
            pk6[j] = (unsigned)slot7(v_sum[2 * (e0 + j)]) |
                     ((unsigned)slot7(v_sum[2 * (e0 + j) + 1]) << 16);
        g_idxA[t] = make_uint4(pk6[0], pk6[1], pk6[2], pk6[3]);
        g_idxB[t] = make_uint2(pk6[4], pk6[5]);
        const int* ev = edge_var + e0;
        g_vsl[t] = make_uint4(
            (unsigned)pslot(ev[0]) | ((unsigned)pslot(ev[1]) << 16),
            (unsigned)pslot(ev[2]) | ((unsigned)pslot(ev[3]) << 16),
            (unsigned)pslot(ev[4]) | ((unsigned)pslot(ev[5]) << 16), 0u);
        g_finidx[t] = make_uint2((unsigned)slot7(fin_idx[3 * t]) |
                                 ((unsigned)slot7(fin_idx[3 * t + 1]) << 16),
                                 (unsigned)slot7(fin_idx[3 * t + 2]));
        g_finw[t] = make_float4(w_final[3 * t] * LN2, w_final[3 * t + 1] * LN2,
                                w_final[3 * t + 2] * LN2, llr_final[t]);
    }
}

// ------------------------------- fast math -----------------------------------
__device__ __forceinline__ float ex2f_(float x) { float y; asm("ex2.approx.f32 %0, %1;" : "=f"(y) : "f"(x)); return y; }
__device__ __forceinline__ float lg2f_(float x) { float y; asm("lg2.approx.f32 %0, %1;" : "=f"(y) : "f"(x)); return y; }
__device__ __forceinline__ float rcpf_(float x) { float y; asm("rcp.approx.f32 %0, %1;" : "=f"(y) : "f"(x)); return y; }

// ---- packed f32x2 (Blackwell) ----
__device__ __forceinline__ u64 pk2(float lo, float hi) {
    u64 r;
    asm("mov.b64 %0, {%1, %2};" : "=l"(r)
        : "r"(__float_as_uint(lo)), "r"(__float_as_uint(hi)));
    return r;
}
__device__ __forceinline__ void upk2(u64 v, float& lo, float& hi) {
    unsigned x, y;
    asm("mov.b64 {%0, %1}, %2;" : "=r"(x), "=r"(y) : "l"(v));
    lo = __uint_as_float(x); hi = __uint_as_float(y);
}
__device__ __forceinline__ u64 fma2_(u64 a, u64 b, u64 c) {
    u64 d; asm("fma.rn.f32x2 %0, %1, %2, %3;" : "=l"(d) : "l"(a), "l"(b), "l"(c)); return d;
}
__device__ __forceinline__ u64 mul2_(u64 a, u64 b) {
    u64 d; asm("mul.rn.f32x2 %0, %1, %2;" : "=l"(d) : "l"(a), "l"(b)); return d;
}
__device__ __forceinline__ u64 add2_(u64 a, u64 b) {
    u64 d; asm("add.rn.f32x2 %0, %1, %2;" : "=l"(d) : "l"(a), "l"(b)); return d;
}

#define ONE2P   0x3F8000003F800000ULL   // {1.0f, 1.0f}
#define NONE2P  0xBF800000BF800000ULL   // {-1.0f, -1.0f}

// msg (2 lanes) = lg2(B + c*A) - lg2(B - c*A), packed until the LG2s.
__device__ __forceinline__ float2 lgmsg(u64 B, u64 A, u64 C2, u64 NC2) {
    u64 U = fma2_(C2, A, B);
    u64 V = fma2_(NC2, A, B);
    float ua, ub, va, vb;
    upk2(U, ua, ub); upk2(V, va, vb);
    return make_float2(lg2f_(ua) - lg2f_(va), lg2f_(ub) - lg2f_(vb));
}

// check node for one packed lane-pair: half-split extrinsic products of (E+1),(E-1).
// Writes message j to dst[2*j + off] (off=0: xy pair, off=1: zw pair) IMMEDIATELY
// (keeps the live set small — this is the pattern that holds 64 regs w/o spill).
__device__ __forceinline__ void tree_packed(const u64* __restrict__ E,
                                            float2* __restrict__ dst, int off) {
    const u64 C2 = pk2(CLIP, CLIP), NC2 = pk2(-CLIP, -CLIP);
    u64 ep3 = add2_(E[3], ONE2P), em3 = add2_(E[3], NONE2P);
    u64 ep4 = add2_(E[4], ONE2P), em4 = add2_(E[4], NONE2P);
    u64 ep5 = add2_(E[5], ONE2P), em5 = add2_(E[5], NONE2P);
    u64 p34 = mul2_(ep3, ep4), m34 = mul2_(em3, em4);
    u64 H2p = mul2_(p34, ep5), H2m = mul2_(m34, em5);

    u64 ep0 = add2_(E[0], ONE2P), em0 = add2_(E[0], NONE2P);
    u64 ep1 = add2_(E[1], ONE2P), em1 = add2_(E[1], NONE2P);
    u64 ep2 = add2_(E[2], ONE2P), em2 = add2_(E[2], NONE2P);
    u64 p01 = mul2_(ep0, ep1), m01 = mul2_(em0, em1);
    u64 H1p = mul2_(p01, ep2), H1m = mul2_(m01, em2);

    dst[0 + off]  = lgmsg(mul2_(mul2_(ep1, ep2), H2p), mul2_(mul2_(em1, em2), H2m), C2, NC2);
    dst[2 + off]  = lgmsg(mul2_(mul2_(ep0, ep2), H2p), mul2_(mul2_(em0, em2), H2m), C2, NC2);
    dst[4 + off]  = lgmsg(mul2_(p01, H2p), mul2_(m01, H2m), C2, NC2);
    dst[6 + off]  = lgmsg(mul2_(mul2_(ep4, ep5), H1p), mul2_(mul2_(em4, em5), H1m), C2, NC2);
    dst[8 + off]  = lgmsg(mul2_(mul2_(ep3, ep5), H1p), mul2_(mul2_(em3, em5), H1m), C2, NC2);
    dst[10 + off] = lgmsg(mul2_(p34, H1p), mul2_(m34, H1m), C2, NC2);
}

// --------------------------------- main --------------------------------------
extern __shared__ float4 s_dyn[];

// One BP iteration (R13 body, buffer-parameterized): read messages at rd_off,
// write new messages at wr_off. ONE barrier, at the end.
#define BP_ITER(rd_off, wr_off, itv)                                            \
    {                                                                           \
        const int base = (itv) * MM + tid;                                      \
        const float4* rd = s_base + (rd_off);                                   \
        float4 wA = g_wA[base], wB = g_wB[base], wC = g_wC[base];               \
        float4 lA = g_lwA[base];                                                \
        float2 lB = g_lwB[base];                                                \
        float w0[6] = { wA.x, wA.z, wB.x, wB.z, wC.x, wC.z };                   \
        float w1[6] = { wA.y, wA.w, wB.y, wB.w, wC.y, wC.w };                   \
        float lw[6] = { lA.x, lA.y, lA.z, lA.w, lB.x, lB.y };                   \
        u64 EL[6], EH[6];                                                       \
        _Pragma("unroll")                                                       \
        for (int j = 0; j < 6; j++) {                                           \
            float4 A  = rd[idx[j] & 0xFFFFu];                                   \
            float4 Bv = rd[idx[j] >> 16];                                       \
            float4 L  = s_base[vsl[j]];                                         \
            u64 w0p = pk2(w0[j], w0[j]);                                        \
            u64 w1p = pk2(w1[j], w1[j]);                                        \
            u64 lwp = pk2(lw[j], lw[j]);                                        \
            u64 uL = fma2_(pk2(A.x, A.y), w0p,                                  \
                     fma2_(pk2(Bv.x, Bv.y), w1p, mul2_(pk2(L.x, L.y), lwp)));   \
            u64 uH = fma2_(pk2(A.z, A.w), w0p,                                  \
                     fma2_(pk2(Bv.z, Bv.w), w1p, mul2_(pk2(L.z, L.w), lwp)));   \
            float u0, u1, u2, u3;                                               \
            upk2(uL, u0, u1); upk2(uH, u2, u3);                                 \
            EL[j] = pk2(ex2f_(fminf(UCLAMP, u0)), ex2f_(fminf(UCLAMP, u1)));    \
            EH[j] = pk2(ex2f_(fminf(UCLAMP, u2)), ex2f_(fminf(UCLAMP, u3)));    \
        }                                                                       \
        float2* dst = (float2*)(s_base + (wr_off)) + tid * (2 * CSTRIDE);       \
        tree_packed(EL, dst, 0);                                                \
        tree_packed(EH, dst, 1);                                                \
        __syncthreads();                                                        \
    }

__global__ void __launch_bounds__(THREADS, 2)
bp_kernel(const float* __restrict__ llr, float* __restrict__ out) {
    float4* s_base = s_dyn;                  // 2 buffers of CSLOTS float4 (112 KB total)
    const int tid = threadIdx.x;
    const long b0 = (long)blockIdx.x * WB;
    const float* llr0 = llr + b0 * NN;

    // zero buf0 (iteration 0 reads zeros from buf0 slots 0..5)
#pragma unroll
    for (int k = 0; k < CSLOTS / THREADS; k++)
        s_base[tid + k * THREADS] = make_float4(0.f, 0.f, 0.f, 0.f);
    __syncthreads();

    // write llr (4 batch lanes per variable) into the pad slots of BOTH buffers
#pragma unroll
    for (int k = 0; k < NN / THREADS; k++) {
        int v = tid + k * THREADS;
        float4 L;
        L.x = llr0[v];
        L.y = llr0[NN + v];
        L.z = llr0[2 * NN + v];
        L.w = llr0[3 * NN + v];
        s_base[pslot(v)] = L;
    }

    // iteration-invariant topology into registers
    uint4 iA = g_idxA[tid];
    uint2 iB = g_idxB[tid];
    uint4 vp = g_vsl[tid];
    unsigned idx[6] = { iA.x, iA.y, iA.z, iA.w, iB.x, iB.y };
    int vsl[6] = { (int)(vp.x & 0xFFFFu), (int)(vp.x >> 16),
                   (int)(vp.y & 0xFFFFu), (int)(vp.y >> 16),
                   (int)(vp.z & 0xFFFFu), (int)(vp.z >> 16) };
    __syncthreads();

    // 10 iterations, ping-pong with compile-time buffer offsets, 1 barrier/iter
#pragma unroll 1
    for (int it2 = 0; it2 < NITERS / 2; it2++) {
        BP_ITER(0, CSLOTS, 2 * it2);
        BP_ITER(CSLOTS, 0, 2 * it2 + 1);
    }

    // final marginalization for variable v = tid (outputs are vars 0..511).
    // After it=9 (odd), last writes went to buf0 -> absolute base indices.
    uint2 fi = g_finidx[tid];
    float4 fw = g_finw[tid];
    float4 A  = s_base[fi.x & 0xFFFFu];
    float4 Bv = s_base[fi.x >> 16];
    float4 C  = s_base[fi.y];
    float4 L  = s_base[pslot(tid)];
    float4 o;
    o.x = fmaf(A.x, fw.x, fmaf(Bv.x, fw.y, fmaf(C.x, fw.z, L.x * fw.w)));
    o.y = fmaf(A.y, fw.x, fmaf(Bv.y, fw.y, fmaf(C.y, fw.z, L.y * fw.w)));
    o.z = fmaf(A.z, fw.x, fmaf(Bv.z, fw.y, fmaf(C.z, fw.z, L.z * fw.w)));
    o.w = fmaf(A.w, fw.x, fmaf(Bv.w, fw.y, fmaf(C.w, fw.z, L.w * fw.w)));
    out[(b0 + 0) * MM + tid] = rcpf_(1.0f + ex2f_(-o.x * LOG2E));
    out[(b0 + 1) * MM + tid] = rcpf_(1.0f + ex2f_(-o.y * LOG2E));
    out[(b0 + 2) * MM + tid] = rcpf_(1.0f + ex2f_(-o.z * LOG2E));
    out[(b0 + 3) * MM + tid] = rcpf_(1.0f + ex2f_(-o.w * LOG2E));
}

// ------------------------------ launch ---------------------------------------
extern "C" void kernel_launch(void* const* d_in, const int* in_sizes, int n_in,
                              void* d_out, int out_size) {
    const float* llr       = (const float*)d_in[0];
    const float* w_iter    = (const float*)d_in[1];
    const float* llr_iter  = (const float*)d_in[2];
    const float* w_final   = (const float*)d_in[3];
    const float* llr_final = (const float*)d_in[4];
    const int*   v_sum     = (const int*)d_in[5];
    // d_in[6] = c_prod_idx: redundant (check r owns edges 6r..6r+5 contiguously)
    const int*   edge_var  = (const int*)d_in[7];
    const int*   fin_idx   = (const int*)d_in[8];

    int B = in_sizes[0] / NN;                 // 8192
    size_t smem = (size_t)(2 * CSLOTS) * sizeof(float4);   // 112 KB

    cudaFuncSetAttribute(bp_kernel, cudaFuncAttributeMaxDynamicSharedMemorySize, (int)smem);

    prep_kernel<<<(NITERS * MM + 255) / 256, 256>>>(w_iter, llr_iter, w_final, llr_final,
                                                    v_sum, edge_var, fin_idx);
    bp_kernel<<<B / WB, THREADS, smem>>>(llr, (float*)d_out);
}